// round 4
// baseline (speedup 1.0000x reference)
#include <cuda_runtime.h>
#include <cstdint>

#define NPROP 8192
#define HID   512
#define NCTA  16          // cluster size for the scan
#define NTHR  416         // 12 weight warps + 1 activation warp

// ---------------- scratch (static device arrays; no runtime alloc) ----------
__device__ float g_conv [(size_t)NPROP * 512];      // conv output, padded 504->512
__device__ float g_feats[(size_t)NPROP * 512];
__device__ float g_Gi   [(size_t)NPROP * 1536];     // reused for encoder then decoder
__device__ float g_hs   [(size_t)NPROP * 512];      // h_{t+1} per step
__device__ float g_decin[(size_t)NPROP * 512];
__device__ float g_WaxPad[512 * 512];               // W_axis padded 504 -> 512 cols

// ---------------- helpers ---------------------------------------------------
__device__ __forceinline__ void fma2(unsigned long long& acc, unsigned long long a,
                                     unsigned long long b) {
    asm("fma.rn.f32x2 %0, %1, %2, %0;" : "+l"(acc) : "l"(a), "l"(b));
}
__device__ __forceinline__ float2 unpack2(unsigned long long v) {
    float2 r; asm("mov.b64 {%0,%1}, %2;" : "=f"(r.x), "=f"(r.y) : "l"(v)); return r;
}
__device__ __forceinline__ float sigm(float x) { return 1.f / (1.f + __expf(-x)); }
__device__ __forceinline__ float tanh_acc(float x) {
    float ax = fabsf(x);
    float e  = __expf(-2.f * ax);
    return copysignf((1.f - e) / (1.f + e), x);
}
__device__ __forceinline__ uint32_t smem_u32(const void* p) {
    uint32_t a;
    asm("{ .reg .u64 t; cvta.to.shared.u64 t, %1; cvt.u32.u64 %0, t; }" : "=r"(a) : "l"(p));
    return a;
}
__device__ __forceinline__ uint32_t mapa_u32(uint32_t local, uint32_t rank) {
    uint32_t r;
    asm("mapa.shared::cluster.u32 %0, %1, %2;" : "=r"(r) : "r"(local), "r"(rank));
    return r;
}
__device__ __forceinline__ unsigned lds_vol(uint32_t a) {
    unsigned v;
    asm volatile("ld.volatile.shared.u32 %0, [%1];" : "=r"(v) : "r"(a) : "memory");
    return v;
}

// ---------------- conv: [N,81,4,4] (x) [56,81,2,2] -> [N,504] (+pad to 512) --
__global__ void conv_kernel(const float* __restrict__ x, const float* __restrict__ Wc,
                            const float* __restrict__ bc) {
    __shared__ float xs[1296];
    const int n = blockIdx.x;
    const float4* xp = (const float4*)(x + (size_t)n * 1296);
    for (int i = threadIdx.x; i < 324; i += 64) ((float4*)xs)[i] = xp[i];
    __syncthreads();
    const int o = threadIdx.x;
    if (o < 56) {
        float acc[9];
        const float b = bc[o];
        #pragma unroll
        for (int p = 0; p < 9; p++) acc[p] = b;
        for (int i = 0; i < 81; i++) {
            float4 wv = *(const float4*)(Wc + o * 324 + i * 4);
            const float* xi = xs + i * 16;
            #pragma unroll
            for (int py = 0; py < 3; py++)
                #pragma unroll
                for (int px = 0; px < 3; px++) {
                    int p = py * 3 + px;
                    acc[p] += xi[py * 4 + px]     * wv.x + xi[py * 4 + px + 1]     * wv.y
                            + xi[(py+1) * 4 + px] * wv.z + xi[(py+1) * 4 + px + 1] * wv.w;
                }
        }
        float* op = g_conv + (size_t)n * 512 + o * 9;
        #pragma unroll
        for (int p = 0; p < 9; p++) op[p] = acc[p];
    } else {
        g_conv[(size_t)n * 512 + 448 + o] = 0.f;
    }
}

// ---------------- pad W_axis [512,504] -> [512,512] --------------------------
__global__ void pad_waxis(const float* __restrict__ W) {
    int idx = blockIdx.x * 256 + threadIdx.x;
    int r = idx >> 9, c = idx & 511;
    g_WaxPad[idx] = (c < 504) ? W[r * 504 + c] : 0.f;
}

// ---------------- SGEMM: C[M,N] (+)= A[M,K] * B[N,K]^T + bias[N] -------------
template <int ACC>
__global__ __launch_bounds__(256)
void sgemm_nt(const float* __restrict__ A, const float* __restrict__ B,
              const float* __restrict__ bias, float* __restrict__ C,
              int M, int N, int K) {
    __shared__ float As[8][128];
    __shared__ float Bs[8][128];
    const int tid = threadIdx.x;
    const int tx = tid & 15, ty = tid >> 4;
    const int lr = tid >> 1;
    const int lc = (tid & 1) << 2;
    const float* Ap = A + (size_t)(blockIdx.y * 128 + lr) * K + lc;
    const float* Bp = B + (size_t)(blockIdx.x * 128 + lr) * K + lc;
    float acc[8][8] = {};
    for (int k0 = 0; k0 < K; k0 += 8) {
        float4 av = *(const float4*)(Ap + k0);
        float4 bv = *(const float4*)(Bp + k0);
        __syncthreads();
        As[lc+0][lr] = av.x; As[lc+1][lr] = av.y; As[lc+2][lr] = av.z; As[lc+3][lr] = av.w;
        Bs[lc+0][lr] = bv.x; Bs[lc+1][lr] = bv.y; Bs[lc+2][lr] = bv.z; Bs[lc+3][lr] = bv.w;
        __syncthreads();
        #pragma unroll
        for (int k = 0; k < 8; k++) {
            float af[8], bf[8];
            *(float4*)(af)     = *(const float4*)&As[k][ty * 8];
            *(float4*)(af + 4) = *(const float4*)&As[k][ty * 8 + 4];
            *(float4*)(bf)     = *(const float4*)&Bs[k][tx * 8];
            *(float4*)(bf + 4) = *(const float4*)&Bs[k][tx * 8 + 4];
            #pragma unroll
            for (int i = 0; i < 8; i++)
                #pragma unroll
                for (int j = 0; j < 8; j++)
                    acc[i][j] += af[i] * bf[j];
        }
    }
    const int row0 = blockIdx.y * 128 + ty * 8;
    const int col0 = blockIdx.x * 128 + tx * 8;
    float bvals[8];
    #pragma unroll
    for (int j = 0; j < 8; j++) bvals[j] = bias[col0 + j];
    #pragma unroll
    for (int i = 0; i < 8; i++) {
        float* cp = C + (size_t)(row0 + i) * N + col0;
        #pragma unroll
        for (int j = 0; j < 8; j += 4) {
            float4 v;
            v.x = acc[i][j+0] + bvals[j+0];
            v.y = acc[i][j+1] + bvals[j+1];
            v.z = acc[i][j+2] + bvals[j+2];
            v.w = acc[i][j+3] + bvals[j+3];
            if (ACC) {
                float4 o = *(const float4*)(cp + j);
                v.x += o.x; v.y += o.y; v.z += o.z; v.w += o.w;
            }
            *(float4*)(cp + j) = v;
        }
    }
}

// ---------------- persistent GRU scan, 16-CTA cluster ------------------------
// CTA c owns h[c*32 .. c*32+31]. 12 weight warps (tid<384) hold 96 Whh rows in
// registers and compute the GEMV; warp 12 (tid>=384) does Gi prefetch (2 steps
// ahead), activations, and DSMEM broadcast. Sync: per-sender flag words
// (st.release.cluster) + local SMEM polling; producer->act handoff via named
// barrier (arrive by weight warps, sync by act warp).
__global__ __launch_bounds__(NTHR, 1)
void scan_kernel(const float* __restrict__ Whh, const float* __restrict__ bhh, int steps) {
    // padded h: element e at (e>>7)*132 + (e&127); two buffers (parity t&1)
    __shared__ float hbuf[2][528];
    __shared__ float hstage[32];
    __shared__ float gh_s[96];
    __shared__ unsigned flags[16];     // flags[c] == t  <=>  h_t slice from CTA c landed

    const int c   = blockIdx.x;
    const int tid = threadIdx.x;
    const int l   = tid & 31;

    // shared init (all threads, before role split)
    for (int i = tid; i < 2 * 528; i += NTHR) ((float*)hbuf)[i] = 0.f;
    if (tid < 16) flags[tid] = 0u;
    __syncthreads();
    asm volatile("barrier.cluster.arrive.aligned;" ::: "memory");
    asm volatile("barrier.cluster.wait.aligned;"   ::: "memory");

    if (tid < 384) {
        // ---------------- weight warps ----------------
        const int row = tid >> 2;          // 0..95
        const int seg = tid & 3;           // 128-float window
        const int gate = row >> 5, j = row & 31;
        const int grow = gate * 512 + c * 32 + j;

        unsigned long long wq[64];
        {
            const ulonglong2* wp = (const ulonglong2*)(Whh + (size_t)grow * 512 + seg * 128);
            #pragma unroll
            for (int i = 0; i < 32; i++) { ulonglong2 t2 = wp[i]; wq[2*i] = t2.x; wq[2*i+1] = t2.y; }
        }
        const float bh = bhh[grow];
        const float* hb0p = &hbuf[0][0] + seg * 132;
        const float* hb1p = &hbuf[1][0] + seg * 132;
        const uint32_t flg = smem_u32(&flags[0]) + 4u * (l & 15);
        const bool poller = (l < 16);

        for (int t = 0; t < steps; t++) {
            // wait until all 16 slices of h_t landed (t=0: flags==0 passes)
            while (!__all_sync(0xffffffffu,
                               !poller || (lds_vol(flg) >= (unsigned)t))) { }
            asm volatile("fence.acq_rel.cluster;" ::: "memory");

            const float* hseg = (t & 1) ? hb1p : hb0p;
            unsigned long long a0 = 0ull, a1 = 0ull;
            #pragma unroll
            for (int i = 0; i < 32; i++) {
                ulonglong2 hv = *(const ulonglong2*)(hseg + i * 4);
                fma2(a0, wq[2*i],   hv.x);
                fma2(a1, wq[2*i+1], hv.y);
            }
            float2 f0 = unpack2(a0), f1 = unpack2(a1);
            float v = (f0.x + f0.y) + (f1.x + f1.y);
            v += __shfl_xor_sync(0xffffffffu, v, 1);
            v += __shfl_xor_sync(0xffffffffu, v, 2);
            if (seg == 0) gh_s[row] = v + bh;
            asm volatile("bar.arrive 1, %0;" :: "r"(NTHR) : "memory");
        }
    } else {
        // ---------------- activation warp ----------------
        // remote addresses: lane i<16 serves peer i (full 128B slice + flag)
        const uint32_t slot_bytes = (uint32_t)(((c >> 2) * 132 + (c & 3) * 32) * 4);
        uint32_t rdst0 = 0, rdst1 = 0, rflag = 0;
        if (l < NCTA) {
            uint32_t hb_loc = smem_u32(&hbuf[0][0]);
            rdst0 = mapa_u32(hb_loc + slot_bytes,           (uint32_t)l);
            rdst1 = mapa_u32(hb_loc + 528u*4u + slot_bytes, (uint32_t)l);
            rflag = mapa_u32(smem_u32(&flags[0]) + 4u * (uint32_t)c, (uint32_t)l);
        }
        float hreg = 0.f;
        const float* gbase = g_Gi + (size_t)c * 32 + l;
        // Gi pipeline: gi (step t), gn (t+1), gf (t+2)
        float gi_r = __ldcs(gbase),          gi_z = __ldcs(gbase + 512),          gi_n = __ldcs(gbase + 1024);
        float gn_r = __ldcs(gbase + 1536),   gn_z = __ldcs(gbase + 1536 + 512),   gn_n = __ldcs(gbase + 1536 + 1024);

        for (int t = 0; t < steps; t++) {
            float gf_r = 0.f, gf_z = 0.f, gf_n = 0.f;
            if (t + 2 < steps) {
                const float* gf = gbase + (size_t)(t + 2) * 1536;
                gf_r = __ldcs(gf); gf_z = __ldcs(gf + 512); gf_n = __ldcs(gf + 1024);
            }
            asm volatile("bar.sync 1, %0;" :: "r"(NTHR) : "memory");   // gh_s ready

            float r = sigm(gi_r + gh_s[l]);
            float z = sigm(gi_z + gh_s[32 + l]);
            float n = tanh_acc(gi_n + r * gh_s[64 + l]);
            hreg = (1.f - z) * n + z * hreg;
            g_hs[(size_t)t * 512 + c * 32 + l] = hreg;                 // fire-and-forget

            if (t + 1 < steps) {
                hstage[l] = hreg;
                __syncwarp();
                if (l < NCTA) {
                    const float4* hs4 = (const float4*)hstage;
                    const uint32_t dst = ((t + 1) & 1) ? rdst1 : rdst0;
                    #pragma unroll
                    for (int i = 0; i < 8; i++) {
                        float4 hv = hs4[i];
                        asm volatile("st.shared::cluster.v4.f32 [%0], {%1,%2,%3,%4};"
                                     :: "r"(dst + 16u * i),
                                        "f"(hv.x), "f"(hv.y), "f"(hv.z), "f"(hv.w) : "memory");
                    }
                    asm volatile("st.release.cluster.shared::cluster.u32 [%0], %1;"
                                 :: "r"(rflag), "r"((unsigned)(t + 1)) : "memory");
                }
            }
            gi_r = gn_r; gi_z = gn_z; gi_n = gn_n;
            gn_r = gf_r; gn_z = gf_z; gn_n = gf_n;
        }
    }
}

// ---------------- decin = relu(feats + enc_final) ----------------------------
__global__ void decin_kernel() {
    int idx = blockIdx.x * 512 + threadIdx.x;
    const float4* f4 = (const float4*)g_feats;
    const float4* e4 = (const float4*)(g_hs + (size_t)8191 * 512);
    float4 f = f4[idx];
    float4 e = e4[idx & 127];
    float4 r;
    r.x = fmaxf(f.x + e.x, 0.f); r.y = fmaxf(f.y + e.y, 0.f);
    r.z = fmaxf(f.z + e.z, 0.f); r.w = fmaxf(f.w + e.w, 0.f);
    ((float4*)g_decin)[idx] = r;
}

// ---------------- out = sigmoid(hs @ W_out^T + b_out) ------------------------
__global__ void out_kernel(const float* __restrict__ Wout, const float* __restrict__ bout,
                           float* __restrict__ out) {
    int row = blockIdx.x * 8 + (threadIdx.x >> 5);
    int l = threadIdx.x & 31;
    const float4* h4 = (const float4*)(g_hs + (size_t)row * 512);
    const float4* w4 = (const float4*)Wout;
    float s = 0.f;
    #pragma unroll
    for (int k = 0; k < 4; k++) {
        float4 h = h4[l + 32 * k], w = w4[l + 32 * k];
        s += h.x * w.x + h.y * w.y + h.z * w.z + h.w * w.w;
    }
    #pragma unroll
    for (int o = 16; o > 0; o >>= 1) s += __shfl_xor_sync(0xffffffffu, s, o);
    if (l == 0) out[row] = sigm(s + bout[0]);
}

// ---------------- launch ------------------------------------------------------
static void launch_scan(const float* Whh, const float* bhh, int steps) {
    static int attr_done = 0;
    if (!attr_done) {
        cudaFuncSetAttribute(scan_kernel, cudaFuncAttributeNonPortableClusterSizeAllowed, 1);
        attr_done = 1;
    }
    cudaLaunchConfig_t cfg = {};
    cfg.gridDim  = dim3(NCTA, 1, 1);
    cfg.blockDim = dim3(NTHR, 1, 1);
    cfg.dynamicSmemBytes = 0;
    cfg.stream = 0;
    cudaLaunchAttribute attrs[1];
    attrs[0].id = cudaLaunchAttributeClusterDimension;
    attrs[0].val.clusterDim.x = NCTA;
    attrs[0].val.clusterDim.y = 1;
    attrs[0].val.clusterDim.z = 1;
    cfg.attrs = attrs;
    cfg.numAttrs = 1;
    cudaLaunchKernelEx(&cfg, scan_kernel, Whh, bhh, steps);
}

extern "C" void kernel_launch(void* const* d_in, const int* in_sizes, int n_in,
                              void* d_out, int out_size) {
    const float* boxes_feature   = (const float*)d_in[0];
    const float* boxes_box_score = (const float*)d_in[1];
    const float* W_app  = (const float*)d_in[2];
    const float* b_app  = (const float*)d_in[3];
    const float* W_conv = (const float*)d_in[4];
    const float* b_conv = (const float*)d_in[5];
    const float* W_axis = (const float*)d_in[6];
    const float* b_axis = (const float*)d_in[7];
    const float* Wih_e  = (const float*)d_in[8];
    const float* Whh_e  = (const float*)d_in[9];
    const float* bih_e  = (const float*)d_in[10];
    const float* bhh_e  = (const float*)d_in[11];
    const float* Wih_d  = (const float*)d_in[12];
    const float* Whh_d  = (const float*)d_in[13];
    const float* bih_d  = (const float*)d_in[14];
    const float* bhh_d  = (const float*)d_in[15];
    const float* W_out  = (const float*)d_in[16];
    const float* b_out  = (const float*)d_in[17];
    float* out = (float*)d_out;

    conv_kernel<<<NPROP, 64>>>(boxes_box_score, W_conv, b_conv);
    pad_waxis<<<1024, 256>>>(W_axis);

    float* feats = nullptr; cudaGetSymbolAddress((void**)&feats, g_feats);
    float* convp = nullptr; cudaGetSymbolAddress((void**)&convp, g_conv);
    float* waxp  = nullptr; cudaGetSymbolAddress((void**)&waxp,  g_WaxPad);
    float* gi    = nullptr; cudaGetSymbolAddress((void**)&gi,    g_Gi);
    float* decin = nullptr; cudaGetSymbolAddress((void**)&decin, g_decin);

    sgemm_nt<0><<<dim3(4, 64), 256>>>(boxes_feature, W_app, b_app, feats, NPROP, 512, 1024);
    sgemm_nt<1><<<dim3(4, 64), 256>>>(convp, waxp, b_axis, feats, NPROP, 512, 512);

    // encoder
    sgemm_nt<0><<<dim3(12, 64), 256>>>(feats, Wih_e, bih_e, gi, NPROP, 1536, 512);
    launch_scan(Whh_e, bhh_e, NPROP);

    // decoder
    decin_kernel<<<2048, 512>>>();
    sgemm_nt<0><<<dim3(12, 64), 256>>>(decin, Wih_d, bih_d, gi, NPROP, 1536, 512);
    launch_scan(Whh_d, bhh_d, NPROP);

    out_kernel<<<1024, 256>>>(W_out, b_out, out);
}